// round 12
// baseline (speedup 1.0000x reference)
#include <cuda_runtime.h>
#include <math.h>

#define FULL 0xffffffffu
typedef unsigned long long ull;
typedef unsigned int u32;

static __device__ __forceinline__ float softplusf(float x) {
    return fmaxf(x, 0.f) + log1pf(expf(-fabsf(x)));
}
static __device__ __forceinline__ float sigmf(float x) {
    return __fdividef(1.f, 1.f + __expf(-x));
}
static __device__ __forceinline__ float tanh_fast(float x) {
    const float e = __expf(2.f * x);
    return 1.f - __fdividef(2.f, e + 1.f);
}
__host__ __device__ constexpr int TRI(int r, int c) { return r * (r + 1) / 2 + c; }

static __device__ __forceinline__ ull fma2(ull a, ull b, ull c) {
    ull d;
    asm("fma.rn.f32x2 %0, %1, %2, %3;" : "=l"(d) : "l"(a), "l"(b), "l"(c));
    return d;
}
static __device__ __forceinline__ float sum2(ull v) {
    u32 l, h;
    asm("mov.b64 {%0, %1}, %2;" : "=r"(l), "=r"(h) : "l"(v));
    return __uint_as_float(l) + __uint_as_float(h);
}
static __device__ __forceinline__ void unpk2(ull v, float& a, float& b) {
    u32 l, h;
    asm("mov.b64 {%0, %1}, %2;" : "=r"(l), "=r"(h) : "l"(v));
    a = __uint_as_float(l); b = __uint_as_float(h);
}
static __device__ __forceinline__ ull packf2(float lo, float hi) {
    ull d;
    asm("mov.b64 %0, {%1, %2};" : "=l"(d) : "r"(__float_as_uint(lo)), "r"(__float_as_uint(hi)));
    return d;
}
#define GBAR() asm volatile("bar.sync %0, 256;" :: "r"(grp + 1) : "memory")

__device__ __constant__ int TRIR[28] = {0,1,1,2,2,2,3,3,3,3,4,4,4,4,4,5,5,5,5,5,5,6,6,6,6,6,6,6};
__device__ __constant__ int TRIC[28] = {0,0,1,0,1,2,0,1,2,3,0,1,2,3,4,0,1,2,3,4,5,0,1,2,3,4,5,6};

// =====================================================================
// k_mass: JVP+VJP+gradV. 512 thr = 2 independent groups of 8 warps.
// Group tile = 16 elements = 32 fwd rows (2e primal, 2e+1 tangent).
// =====================================================================
#define MW1   0
#define MB1   896
#define MB2   1024
#define MB3   1152
#define PW    1184
#define PB    2080
#define SP2   2208
#define W2P   2336      // [kp64][2i+p]
#define W3P   18720     // [ip64][2t+p]
#define MGRP  22304
#define GSZ   14416
// group-relative:
#define gXIN  0         // [16][24]
#define gH1   384       // [32][130]
#define gH2   4544      // [32][130]
#define gA3   8704      // [32][30]
#define gGH   9664      // [16][29]
#define gTA   10128     // [16][8]
#define gBZ2  10256     // [16][130]
#define gBZ1  12336     // [16][130]
#define M_TOT (MGRP + 2 * GSZ)

__global__ __launch_bounds__(512, 1) void k_mass(
    const float* __restrict__ q, const float* __restrict__ dq, const float* __restrict__ ddq,
    const float* __restrict__ mW1, const float* __restrict__ mb1,
    const float* __restrict__ mW2, const float* __restrict__ mb2,
    const float* __restrict__ mW3, const float* __restrict__ mb3,
    const float* __restrict__ pW1, const float* __restrict__ pb1,
    const float* __restrict__ pw2,
    float* __restrict__ out, int batch)
{
    extern __shared__ float smf[];
    const int tid = threadIdx.x;
    const int lane = tid & 31;
    const int warp = tid >> 5;
    const int grp = warp >> 3;
    const int wg = warp & 7;

    for (int i = tid; i < 896; i += 512) { smf[MW1 + i] = mW1[i]; smf[PW + i] = pW1[i]; }
    for (int i = tid; i < 128; i += 512) {
        smf[MB1 + i] = mb1[i]; smf[MB2 + i] = mb2[i];
        smf[PB + i] = pb1[i]; smf[SP2 + i] = softplusf(pw2[i]);
    }
    for (int i = tid; i < 32; i += 512) smf[MB3 + i] = (i < 28) ? mb3[i] : 0.f;
    for (int idx = tid; idx < 16384; idx += 512) {
        const int kp = idx >> 8, r = idx & 255;
        smf[W2P + idx] = mW2[(2 * kp + (r & 1)) * 128 + (r >> 1)];
    }
    for (int idx = tid; idx < 3584; idx += 512) {
        const int kp = idx / 56, r = idx % 56;
        smf[W3P + idx] = mW3[(2 * kp + (r & 1)) * 28 + (r >> 1)];
    }
    __syncthreads();

    float* g = smf + MGRP + grp * GSZ;
    const int gt = tid & 255;
    const int i1 = tid & 127;
    const int eh = (tid >> 7) & 1;
    float w1r[7];
#pragma unroll
    for (int d = 0; d < 7; d++) w1r[d] = smf[MW1 + d * 128 + i1];
    const float b1r = smf[MB1 + i1];

    const int ntiles = (batch + 15) >> 4;
    for (int tile = blockIdx.x * 2 + grp; tile < ntiles; tile += gridDim.x * 2) {
        const int b0 = tile << 4;

        // 1. stage XIN [16][24]
        for (int idx = gt; idx < 384; idx += 256) {
            const int e = idx / 24, s = idx % 24;
            const int b = b0 + e;
            float v = 0.f;
            if (b < batch) {
                if (s < 7) v = q[b * 7 + s];
                else if (s >= 8 && s < 15) v = dq[b * 7 + s - 8];
                else if (s >= 16 && s < 23) v = ddq[b * 7 + s - 16];
            }
            g[gXIN + idx] = v;
        }
        GBAR();

        // 2. layer1 primal + tangent
#pragma unroll
        for (int it = 0; it < 8; it++) {
            const int e = eh * 8 + it;
            const float* xe = g + gXIN + e * 24;
            float z = b1r, dz = 0.f;
#pragma unroll
            for (int d = 0; d < 7; d++) {
                z = fmaf(xe[d], w1r[d], z);
                dz = fmaf(xe[8 + d], w1r[d], dz);
            }
            const float h = tanh_fast(z);
            g[gH1 + (2 * e) * 130 + i1] = h;
            g[gH1 + (2 * e + 1) * 130 + i1] = (1.f - h * h) * dz;
        }
        GBAR();

        // 3. fwd L2: warp -> 16 outs, lane = row
        {
            ull acc[16];
#pragma unroll
            for (int m = 0; m < 16; m++) acc[m] = 0ull;
            const float* x0 = g + gH1 + lane * 130;
            const float* wb = smf + W2P + wg * 32;
#pragma unroll 2
            for (int kp = 0; kp < 64; kp++) {
                const ull xa = *(const ull*)(x0 + 2 * kp);
                const float* wr = wb + kp * 256;
#pragma unroll
                for (int m = 0; m < 8; m++) {
                    const double2 wd = *(const double2*)(wr + 4 * m);
                    acc[2 * m]     = fma2(xa, __double_as_longlong(wd.x), acc[2 * m]);
                    acc[2 * m + 1] = fma2(xa, __double_as_longlong(wd.y), acc[2 * m + 1]);
                }
            }
            // 4. epilogue
            const int psrc = lane & ~1;
            const bool prim = (lane & 1) == 0;
#pragma unroll
            for (int j = 0; j < 16; j += 2) {
                const float za = sum2(acc[j]), zb = sum2(acc[j + 1]);
                float ha = 0.f, hb = 0.f, ga = 0.f, gb2 = 0.f;
                if (prim) {
                    ha = tanh_fast(za + smf[MB2 + wg * 16 + j]);
                    hb = tanh_fast(zb + smf[MB2 + wg * 16 + j + 1]);
                    ga = 1.f - ha * ha;
                    gb2 = 1.f - hb * hb;
                }
                const float sa = __shfl_sync(FULL, ga, psrc);
                const float sb = __shfl_sync(FULL, gb2, psrc);
                const float va = prim ? ha : sa * za;
                const float vb = prim ? hb : sb * zb;
                *(ull*)&g[gH2 + lane * 130 + wg * 16 + j] = packf2(va, vb);
            }
        }
        GBAR();

        // 5. fwd L3: warps wg<7 -> 4 outs, lane = row
        if (wg < 7) {
            const int t0 = wg * 4;
            ull a4[4] = {0ull, 0ull, 0ull, 0ull};
            const float* x0 = g + gH2 + lane * 130;
            const float* wb = smf + W3P + wg * 8;
#pragma unroll 2
            for (int kp = 0; kp < 64; kp++) {
                const ull xa = *(const ull*)(x0 + 2 * kp);
                const double2 w0 = *(const double2*)(wb + kp * 56);
                const double2 w1 = *(const double2*)(wb + kp * 56 + 4);
                a4[0] = fma2(xa, __double_as_longlong(w0.x), a4[0]);
                a4[1] = fma2(xa, __double_as_longlong(w0.y), a4[1]);
                a4[2] = fma2(xa, __double_as_longlong(w1.x), a4[2]);
                a4[3] = fma2(xa, __double_as_longlong(w1.y), a4[3]);
            }
            const bool prim = (lane & 1) == 0;
#pragma unroll
            for (int j = 0; j < 4; j++)
                g[gA3 + lane * 30 + t0 + j] = sum2(a4[j]) + (prim ? smf[MB3 + t0 + j] : 0.f);
        }
        GBAR();

        // 6. mini-assembly: L, sig, u0, tauA, cotangent ghat
#pragma unroll 1
        for (int rr = 0; rr < 2; rr++) {
            const int e = rr * 8 + wg;
            if (b0 + e < batch) {
                float dqv = 0.f, ddqv = 0.f;
                if (lane < 7) {
                    dqv = g[gXIN + e * 24 + 8 + lane];
                    ddqv = g[gXIN + e * 24 + 16 + lane];
                }
                const float* ap = g + gA3 + (2 * e) * 30;
                const float* at = g + gA3 + (2 * e + 1) * 30;
                float Lm[28], Db[28], sig[7];
#pragma unroll
                for (int t = 0; t < 28; t++) { Lm[t] = ap[t]; Db[t] = at[t]; }
#pragma unroll
                for (int r = 0; r < 7; r++) {
                    const int td = TRI(r, r);
                    const float p = Lm[td];
                    sig[r] = sigmf(p);
                    Lm[td] = softplusf(p);
                    Db[td] *= sig[r];
                }
                float dqs[7], dds[7];
#pragma unroll
                for (int r = 0; r < 7; r++) {
                    dqs[r] = __shfl_sync(FULL, dqv, r);
                    dds[r] = __shfl_sync(FULL, ddqv, r);
                }
                float u0[7], t2[7], wv[7];
#pragma unroll
                for (int c = 0; c < 7; c++) {
                    float s = 0.f, s2 = 0.f, s3 = 0.f;
#pragma unroll
                    for (int r = 0; r < 7; r++) {
                        if (r >= c) {
                            const int t = TRI(r, c);
                            s = fmaf(Lm[t], dqs[r], s);
                            s2 = fmaf(Lm[t], dds[r], s2);
                            s3 = fmaf(Db[t], dqs[r], s3);
                        }
                    }
                    u0[c] = s; t2[c] = s2; wv[c] = s3;
                }
                float tsel = 0.f;
#pragma unroll
                for (int i = 0; i < 7; i++) {
                    float s = 0.f;
#pragma unroll
                    for (int c = 0; c <= i; c++) {
                        s = fmaf(Lm[TRI(i, c)], t2[c] + wv[c], s);
                        s = fmaf(Db[TRI(i, c)], u0[c], s);
                    }
                    if (lane == i) tsel = s;
                }
                if (lane < 7) g[gTA + e * 8 + lane] = tsel;
                if (lane < 28) {
                    const int r = TRIR[lane], c = TRIC[lane];
                    float gg = dqs[r] * u0[c];
                    if (r == c) gg *= sig[r];
                    g[gGH + e * 29 + lane] = gg;
                }
            }
        }
        GBAR();

        // 7. bwd L3 (splat): warp -> 8 i-pairs; lane = (element, t-half)
        {
            const int el = lane & 15, th = lane >> 4;
            ull acc[8];
#pragma unroll
            for (int m = 0; m < 8; m++) acc[m] = 0ull;
            const float* gh = g + gGH + el * 29;
            const int tb = th * 14;
#pragma unroll
            for (int t2i = 0; t2i < 14; t2i++) {
                const int t = tb + t2i;
                const float gv = gh[t];
                const ull gs = packf2(gv, gv);
#pragma unroll
                for (int m = 0; m < 8; m++)
                    acc[m] = fma2(gs, *(const ull*)&smf[W3P + (wg * 8 + m) * 56 + 2 * t], acc[m]);
            }
#pragma unroll
            for (int m = 0; m < 8; m++) {
                float fa, fb; unpk2(acc[m], fa, fb);
                fa += __shfl_xor_sync(FULL, fa, 16);
                fb += __shfl_xor_sync(FULL, fb, 16);
                if (th == 0) {
                    const int i0 = wg * 16 + 2 * m;
                    float h0, h1;
                    unpk2(*(const ull*)&g[gH2 + (2 * el) * 130 + i0], h0, h1);
                    *(ull*)&g[gBZ2 + el * 130 + i0] =
                        packf2((1.f - h0 * h0) * fa, (1.f - h1 * h1) * fb);
                }
            }
        }
        GBAR();

        // 8. bwd L2 (splat): warp -> 8 k-pairs; lane = (element, i-half)
        {
            const int el = lane & 15, ih = lane >> 4;
            ull acc[8];
#pragma unroll
            for (int m = 0; m < 8; m++) acc[m] = 0ull;
            const float* bz = g + gBZ2 + el * 130 + ih * 64;
            const float* wkb = smf + W2P + ih * 128;
#pragma unroll 4
            for (int ii = 0; ii < 64; ii++) {
                const float bv = bz[ii];
                const ull s = packf2(bv, bv);
#pragma unroll
                for (int m = 0; m < 8; m++)
                    acc[m] = fma2(s, *(const ull*)(wkb + (wg * 8 + m) * 256 + 2 * ii), acc[m]);
            }
#pragma unroll
            for (int m = 0; m < 8; m++) {
                float fa, fb; unpk2(acc[m], fa, fb);
                fa += __shfl_xor_sync(FULL, fa, 16);
                fb += __shfl_xor_sync(FULL, fb, 16);
                if (ih == 0) {
                    const int k0 = wg * 16 + 2 * m;
                    float h0, h1;
                    unpk2(*(const ull*)&g[gH1 + (2 * el) * 130 + k0], h0, h1);
                    *(ull*)&g[gBZ1 + el * 130 + k0] =
                        packf2((1.f - h0 * h0) * fa, (1.f - h1 * h1) * fb);
                }
            }
        }
        GBAR();

        // 9. bwd L1 + gradV + output
#pragma unroll 1
        for (int rr = 0; rr < 2; rr++) {
            const int e = rr * 8 + wg;
            const int b = b0 + e;
            if (b < batch) {
                float qv = 0.f;
                if (lane < 7) qv = g[gXIN + e * 24 + lane];
                float qs[7];
#pragma unroll
                for (int r = 0; r < 7; r++) qs[r] = __shfl_sync(FULL, qv, r);
                float acc7[7] = {0.f, 0.f, 0.f, 0.f, 0.f, 0.f, 0.f};
#pragma unroll
                for (int m4 = 0; m4 < 4; m4++) {
                    const int k = m4 * 32 + lane;
                    const float bv = g[gBZ1 + e * 130 + k];
#pragma unroll
                    for (int j = 0; j < 7; j++) acc7[j] = fmaf(-smf[MW1 + j * 128 + k], bv, acc7[j]);
                }
#pragma unroll
                for (int hh = 0; hh < 4; hh++) {
                    const int h = hh * 32 + lane;
                    float wvv[7];
                    float z = smf[PB + h];
#pragma unroll
                    for (int d = 0; d < 7; d++) {
                        wvv[d] = smf[PW + d * 128 + h];
                        z = fmaf(qs[d], wvv[d], z);
                    }
                    const float s = sigmf(z) * smf[SP2 + h];
#pragma unroll
                    for (int d = 0; d < 7; d++) acc7[d] = fmaf(wvv[d], s, acc7[d]);
                }
#pragma unroll
                for (int j = 0; j < 7; j++) {
                    acc7[j] += __shfl_xor_sync(FULL, acc7[j], 16);
                    acc7[j] += __shfl_xor_sync(FULL, acc7[j], 8);
                    acc7[j] += __shfl_xor_sync(FULL, acc7[j], 4);
                    acc7[j] += __shfl_xor_sync(FULL, acc7[j], 2);
                    acc7[j] += __shfl_xor_sync(FULL, acc7[j], 1);
                }
                float sel = 0.f;
#pragma unroll
                for (int j = 0; j < 7; j++) if (lane == j) sel = acc7[j];
                if (lane < 7) out[b * 7 + lane] = g[gTA + e * 8 + lane] + sel;
            }
        }
        GBAR();
    }
}

// =====================================================================
// k_damp: 2 groups of 8 warps; group tile = 64 elements.
// =====================================================================
#define DW1   0
#define DB1   1792
#define DB2   1920
#define DW2P  2048
#define DW3P  18432
#define DB3   22016
#define DGRP  22048
#define DGSZ  16640
#define dH1   0         // [64][130]; DA3 overlay [64][33]
#define dH2   8320      // [64][130]; XIN overlay [64][14]
#define D_TOT (DGRP + 2 * DGSZ)

__global__ __launch_bounds__(512, 1) void k_damp(
    const float* __restrict__ q, const float* __restrict__ dq,
    const float* __restrict__ dW1, const float* __restrict__ db1,
    const float* __restrict__ dW2, const float* __restrict__ db2,
    const float* __restrict__ dW3, const float* __restrict__ db3,
    float* __restrict__ out, int batch)
{
    extern __shared__ float smf[];
    const int tid = threadIdx.x;
    const int lane = tid & 31;
    const int warp = tid >> 5;
    const int grp = warp >> 3;
    const int wg = warp & 7;

    for (int i = tid; i < 1792; i += 512) smf[DW1 + i] = dW1[i];
    for (int i = tid; i < 128; i += 512) { smf[DB1 + i] = db1[i]; smf[DB2 + i] = db2[i]; }
    for (int idx = tid; idx < 16384; idx += 512) {
        const int kp = idx >> 8, r = idx & 255;
        smf[DW2P + idx] = dW2[(2 * kp + (r & 1)) * 128 + (r >> 1)];
    }
    for (int idx = tid; idx < 3584; idx += 512) {
        const int kp = idx / 56, r = idx % 56;
        smf[DW3P + idx] = dW3[(2 * kp + (r & 1)) * 28 + (r >> 1)];
    }
    for (int i = tid; i < 32; i += 512) smf[DB3 + i] = (i < 28) ? db3[i] : 0.f;
    __syncthreads();

    float* g = smf + DGRP + grp * DGSZ;
    const int gt = tid & 255;
    const int i1 = tid & 127;
    const int eh = (tid >> 7) & 1;
    float w1r[14];
#pragma unroll
    for (int d = 0; d < 14; d++) w1r[d] = smf[DW1 + d * 128 + i1];
    const float b1r = smf[DB1 + i1];

    const int ntiles = (batch + 63) >> 6;
    for (int tile = blockIdx.x * 2 + grp; tile < ntiles; tile += gridDim.x * 2) {
        const int b0 = tile << 6;

        // stage XIN [64][14] in dH2 region
        for (int idx = gt; idx < 896; idx += 256) {
            const int e = idx / 14, d = idx % 14;
            const int b = b0 + e;
            float v = 0.f;
            if (b < batch) v = (d < 7) ? q[b * 7 + d] : dq[b * 7 + d - 7];
            g[dH2 + idx] = v;
        }
        GBAR();

        // layer 1
#pragma unroll 2
        for (int it = 0; it < 32; it++) {
            const int e = eh * 32 + it;
            const float* xe = g + dH2 + e * 14;
            float z = b1r;
#pragma unroll
            for (int d = 0; d < 14; d++) z = fmaf(xe[d], w1r[d], z);
            g[dH1 + e * 130 + i1] = tanh_fast(z);
        }
        GBAR();

        // fwd L2: warp -> 16 outs, rows (lane, lane+32)
        {
            ull acc0[16], acc1[16];
#pragma unroll
            for (int ii = 0; ii < 16; ii++) { acc0[ii] = 0ull; acc1[ii] = 0ull; }
            const float* x0 = g + dH1 + lane * 130;
            const float* x1 = g + dH1 + (lane + 32) * 130;
            const float* wb = smf + DW2P + wg * 32;
#pragma unroll 1
            for (int kp = 0; kp < 64; kp++) {
                const ull xa = *(const ull*)(x0 + 2 * kp);
                const ull xb = *(const ull*)(x1 + 2 * kp);
                const float* wr = wb + kp * 256;
#pragma unroll
                for (int m = 0; m < 8; m++) {
                    const double2 wd = *(const double2*)(wr + 4 * m);
                    const ull wx = __double_as_longlong(wd.x);
                    const ull wy = __double_as_longlong(wd.y);
                    acc0[2 * m]     = fma2(xa, wx, acc0[2 * m]);
                    acc1[2 * m]     = fma2(xb, wx, acc1[2 * m]);
                    acc0[2 * m + 1] = fma2(xa, wy, acc0[2 * m + 1]);
                    acc1[2 * m + 1] = fma2(xb, wy, acc1[2 * m + 1]);
                }
            }
            float* y0 = g + dH2 + lane * 130 + wg * 16;
            float* y1 = g + dH2 + (lane + 32) * 130 + wg * 16;
#pragma unroll
            for (int m = 0; m < 8; m++) {
                const float ba = smf[DB2 + wg * 16 + 2 * m];
                const float bb = smf[DB2 + wg * 16 + 2 * m + 1];
                const float v0a = tanh_fast(sum2(acc0[2 * m]) + ba);
                const float v0b = tanh_fast(sum2(acc0[2 * m + 1]) + bb);
                const float v1a = tanh_fast(sum2(acc1[2 * m]) + ba);
                const float v1b = tanh_fast(sum2(acc1[2 * m + 1]) + bb);
                *(ull*)(y0 + 2 * m) = packf2(v0a, v0b);
                *(ull*)(y1 + 2 * m) = packf2(v1a, v1b);
            }
        }
        GBAR();

        // fwd L3 (wg<7): 4 outs, rows (lane, lane+32); A3 overlays dH1 stride 33
        if (wg < 7) {
            ull a0[4] = {0,0,0,0}, a1[4] = {0,0,0,0};
            const float* x0 = g + dH2 + lane * 130;
            const float* x1 = g + dH2 + (lane + 32) * 130;
            const float* wb = smf + DW3P + wg * 8;
#pragma unroll 1
            for (int kp = 0; kp < 64; kp++) {
                const ull xa = *(const ull*)(x0 + 2 * kp);
                const ull xb = *(const ull*)(x1 + 2 * kp);
                const double2 w0 = *(const double2*)(wb + kp * 56);
                const double2 w1 = *(const double2*)(wb + kp * 56 + 4);
                const ull wA = __double_as_longlong(w0.x), wB = __double_as_longlong(w0.y);
                const ull wC = __double_as_longlong(w1.x), wD = __double_as_longlong(w1.y);
                a0[0] = fma2(xa, wA, a0[0]); a1[0] = fma2(xb, wA, a1[0]);
                a0[1] = fma2(xa, wB, a0[1]); a1[1] = fma2(xb, wB, a1[1]);
                a0[2] = fma2(xa, wC, a0[2]); a1[2] = fma2(xb, wC, a1[2]);
                a0[3] = fma2(xa, wD, a0[3]); a1[3] = fma2(xb, wD, a1[3]);
            }
#pragma unroll
            for (int j = 0; j < 4; j++) {
                const int i = wg * 4 + j;
                const float bb = smf[DB3 + i];
                g[dH1 + lane * 33 + i] = sum2(a0[j]) + bb;
                g[dH1 + (lane + 32) * 33 + i] = sum2(a1[j]) + bb;
            }
        }
        GBAR();

        // assembly: 8 rounds, warp-per-element
#pragma unroll 1
        for (int rr = 0; rr < 8; rr++) {
            const int e = rr * 8 + wg;
            const int b = b0 + e;
            if (b < batch) {
                float dqv = 0.f;
                if (lane < 7) dqv = dq[b * 7 + lane];
                float dqs[7];
#pragma unroll
                for (int r = 0; r < 7; r++) dqs[r] = __shfl_sync(FULL, dqv, r);
                const float* scr = g + dH1 + e * 33;
                float Lm[28];
#pragma unroll
                for (int t = 0; t < 28; t++) Lm[t] = scr[t];
#pragma unroll
                for (int r = 0; r < 7; r++) Lm[TRI(r, r)] = softplusf(Lm[TRI(r, r)]);
                float u[7];
#pragma unroll
                for (int c = 0; c < 7; c++) {
                    float s = 0.f;
#pragma unroll
                    for (int r = 0; r < 7; r++)
                        if (r >= c) s = fmaf(Lm[TRI(r, c)], dqs[r], s);
                    u[c] = s;
                }
                float outsel = 0.f;
#pragma unroll
                for (int i = 0; i < 7; i++) {
                    float s = 0.f;
#pragma unroll
                    for (int c = 0; c <= i; c++) s = fmaf(Lm[TRI(i, c)], u[c], s);
                    if (lane == i) outsel = s;
                }
                if (lane < 7) out[b * 7 + lane] += outsel;
            }
        }
        GBAR();
    }
}

// =====================================================================
extern "C" void kernel_launch(void* const* d_in, const int* in_sizes, int n_in,
                              void* d_out, int out_size)
{
    const float* q   = (const float*)d_in[0];
    const float* dq  = (const float*)d_in[1];
    const float* ddq = (const float*)d_in[2];
    const float* mW1 = (const float*)d_in[3];
    const float* mb1 = (const float*)d_in[4];
    const float* mW2 = (const float*)d_in[5];
    const float* mb2 = (const float*)d_in[6];
    const float* mW3 = (const float*)d_in[7];
    const float* mb3 = (const float*)d_in[8];
    const float* dW1 = (const float*)d_in[9];
    const float* db1 = (const float*)d_in[10];
    const float* dW2 = (const float*)d_in[11];
    const float* db2 = (const float*)d_in[12];
    const float* dW3 = (const float*)d_in[13];
    const float* db3 = (const float*)d_in[14];
    const float* pW1 = (const float*)d_in[15];
    const float* pb1 = (const float*)d_in[16];
    const float* pw2 = (const float*)d_in[17];
    float* out = (float*)d_out;

    const int batch = in_sizes[0] / 7;

    const size_t sm1 = (size_t)M_TOT * sizeof(float);
    const size_t sm2 = (size_t)D_TOT * sizeof(float);

    cudaFuncSetAttribute(k_mass, cudaFuncAttributeMaxDynamicSharedMemorySize, (int)sm1);
    cudaFuncSetAttribute(k_damp, cudaFuncAttributeMaxDynamicSharedMemorySize, (int)sm2);

    k_mass<<<148, 512, sm1>>>(q, dq, ddq, mW1, mb1, mW2, mb2, mW3, mb3,
                              pW1, pb1, pw2, out, batch);
    k_damp<<<148, 512, sm2>>>(q, dq, dW1, db1, dW2, db2, dW3, db3, out, batch);
}

// round 13
// speedup vs baseline: 1.0525x; 1.0525x over previous
#include <cuda_runtime.h>
#include <math.h>

#define FULL 0xffffffffu
typedef unsigned long long ull;
typedef unsigned int u32;

static __device__ __forceinline__ float softplusf(float x) {
    return fmaxf(x, 0.f) + log1pf(expf(-fabsf(x)));
}
static __device__ __forceinline__ float sigmf(float x) {
    return __fdividef(1.f, 1.f + __expf(-x));
}
static __device__ __forceinline__ float tanh_fast(float x) {
    const float e = __expf(2.f * x);
    return 1.f - __fdividef(2.f, e + 1.f);
}
__host__ __device__ constexpr int TRI(int r, int c) { return r * (r + 1) / 2 + c; }

static __device__ __forceinline__ ull fma2(ull a, ull b, ull c) {
    ull d;
    asm("fma.rn.f32x2 %0, %1, %2, %3;" : "=l"(d) : "l"(a), "l"(b), "l"(c));
    return d;
}
static __device__ __forceinline__ float sum2(ull v) {
    u32 l, h;
    asm("mov.b64 {%0, %1}, %2;" : "=r"(l), "=r"(h) : "l"(v));
    return __uint_as_float(l) + __uint_as_float(h);
}
static __device__ __forceinline__ void unpk2(ull v, float& a, float& b) {
    u32 l, h;
    asm("mov.b64 {%0, %1}, %2;" : "=r"(l), "=r"(h) : "l"(v));
    a = __uint_as_float(l); b = __uint_as_float(h);
}
static __device__ __forceinline__ ull packf2(float lo, float hi) {
    ull d;
    asm("mov.b64 %0, {%1, %2};" : "=l"(d) : "r"(__float_as_uint(lo)), "r"(__float_as_uint(hi)));
    return d;
}
static __device__ __forceinline__ ull ll(double d) { return __double_as_longlong(d); }
#define GBAR() asm volatile("bar.sync %0, 256;" :: "r"(grp + 1) : "memory")

__device__ __constant__ int TRIR[28] = {0,1,1,2,2,2,3,3,3,3,4,4,4,4,4,5,5,5,5,5,5,6,6,6,6,6,6,6};
__device__ __constant__ int TRIC[28] = {0,0,1,0,1,2,0,1,2,3,0,1,2,3,4,0,1,2,3,4,5,0,1,2,3,4,5,6};

// =====================================================================
// k_mass: JVP+VJP+gradV. R11 single-group structure (tile=32 elements,
// 64 fwd rows), with widened (LDS.128) backward weight loads.
// =====================================================================
#define MW1   0
#define MB1   896
#define MB2   1024
#define MB3   1152
#define PW    1184
#define PB    2080
#define SP2   2208
#define W2P   2336
#define W3P   18720
#define MXIN  22304
#define MH1   23072
#define MH2   31392
#define MA3   39712
#define MGH   41632
#define MTA   42560
#define BZ2   42816
#define BZ1   46976
#define M_TOT 51136

__global__ __launch_bounds__(512, 1) void k_mass(
    const float* __restrict__ q, const float* __restrict__ dq, const float* __restrict__ ddq,
    const float* __restrict__ mW1, const float* __restrict__ mb1,
    const float* __restrict__ mW2, const float* __restrict__ mb2,
    const float* __restrict__ mW3, const float* __restrict__ mb3,
    const float* __restrict__ pW1, const float* __restrict__ pb1,
    const float* __restrict__ pw2,
    float* __restrict__ out, int batch)
{
    extern __shared__ float smf[];
    const int tid = threadIdx.x;
    const int lane = tid & 31;
    const int warp = tid >> 5;

    for (int i = tid; i < 896; i += 512) { smf[MW1 + i] = mW1[i]; smf[PW + i] = pW1[i]; }
    for (int i = tid; i < 128; i += 512) {
        smf[MB1 + i] = mb1[i]; smf[MB2 + i] = mb2[i];
        smf[PB + i] = pb1[i]; smf[SP2 + i] = softplusf(pw2[i]);
    }
    for (int i = tid; i < 32; i += 512) smf[MB3 + i] = (i < 28) ? mb3[i] : 0.f;
    for (int idx = tid; idx < 16384; idx += 512) {
        const int kp = idx >> 8, r = idx & 255;
        smf[W2P + idx] = mW2[(2 * kp + (r & 1)) * 128 + (r >> 1)];
    }
    for (int idx = tid; idx < 3584; idx += 512) {
        const int kp = idx / 56, r = idx % 56;
        smf[W3P + idx] = mW3[(2 * kp + (r & 1)) * 28 + (r >> 1)];
    }
    __syncthreads();

    const int i1 = tid & 127;
    const int eg = tid >> 7;
    float w1r[7];
#pragma unroll
    for (int d = 0; d < 7; d++) w1r[d] = smf[MW1 + d * 128 + i1];
    const float b1r = smf[MB1 + i1];

    const int ntiles = (batch + 31) >> 5;
    for (int tile = blockIdx.x; tile < ntiles; tile += gridDim.x) {
        const int b0 = tile << 5;

        // 1. stage XIN
        for (int idx = tid; idx < 768; idx += 512) {
            const int e = idx / 24, s = idx % 24;
            const int b = b0 + e;
            float v = 0.f;
            if (b < batch) {
                if (s < 7) v = q[b * 7 + s];
                else if (s >= 8 && s < 15) v = dq[b * 7 + s - 8];
                else if (s >= 16 && s < 23) v = ddq[b * 7 + s - 16];
            }
            smf[MXIN + idx] = v;
        }
        __syncthreads();

        // 2. layer1 primal + tangent
#pragma unroll
        for (int it = 0; it < 8; it++) {
            const int e = eg * 8 + it;
            const float* xe = &smf[MXIN + e * 24];
            float z = b1r, dz = 0.f;
#pragma unroll
            for (int d = 0; d < 7; d++) {
                z = fmaf(xe[d], w1r[d], z);
                dz = fmaf(xe[8 + d], w1r[d], dz);
            }
            const float h = tanh_fast(z);
            smf[MH1 + (2 * e) * 130 + i1] = h;
            smf[MH1 + (2 * e + 1) * 130 + i1] = (1.f - h * h) * dz;
        }
        __syncthreads();

        // 3. fwd L2: warp -> 8 outs, lane rows (lane, lane+32)
        {
            ull acc[16];
#pragma unroll
            for (int m = 0; m < 16; m++) acc[m] = 0ull;
            const float* x0 = &smf[MH1 + lane * 130];
            const float* x1 = &smf[MH1 + (lane + 32) * 130];
            const float* wb = &smf[W2P + warp * 16];
#pragma unroll 2
            for (int kp = 0; kp < 64; kp++) {
                const ull xa = *(const ull*)(x0 + 2 * kp);
                const ull xb = *(const ull*)(x1 + 2 * kp);
                const float* wr = wb + kp * 256;
#pragma unroll
                for (int m = 0; m < 4; m++) {
                    const double2 wd = *(const double2*)(wr + 4 * m);
                    const ull wx = ll(wd.x), wy = ll(wd.y);
                    acc[2 * m]         = fma2(xa, wx, acc[2 * m]);
                    acc[2 * m + 1]     = fma2(xa, wy, acc[2 * m + 1]);
                    acc[8 + 2 * m]     = fma2(xb, wx, acc[8 + 2 * m]);
                    acc[8 + 2 * m + 1] = fma2(xb, wy, acc[8 + 2 * m + 1]);
                }
            }
            // 4. epilogue
            const int psrc = lane & ~1;
            const bool prim = (lane & 1) == 0;
#pragma unroll
            for (int j = 0; j < 8; j += 2) {
                const float z0a = sum2(acc[j]),     z0b = sum2(acc[j + 1]);
                const float z1a = sum2(acc[8 + j]), z1b = sum2(acc[8 + j + 1]);
                float h0a = 0.f, h0b = 0.f, h1a = 0.f, h1b = 0.f;
                float g0a = 0.f, g0b = 0.f, g1a = 0.f, g1b = 0.f;
                if (prim) {
                    const float ba = smf[MB2 + warp * 8 + j];
                    const float bb = smf[MB2 + warp * 8 + j + 1];
                    h0a = tanh_fast(z0a + ba); g0a = 1.f - h0a * h0a;
                    h0b = tanh_fast(z0b + bb); g0b = 1.f - h0b * h0b;
                    h1a = tanh_fast(z1a + ba); g1a = 1.f - h1a * h1a;
                    h1b = tanh_fast(z1b + bb); g1b = 1.f - h1b * h1b;
                }
                const float s0a = __shfl_sync(FULL, g0a, psrc);
                const float s0b = __shfl_sync(FULL, g0b, psrc);
                const float s1a = __shfl_sync(FULL, g1a, psrc);
                const float s1b = __shfl_sync(FULL, g1b, psrc);
                const float v0a = prim ? h0a : s0a * z0a;
                const float v0b = prim ? h0b : s0b * z0b;
                const float v1a = prim ? h1a : s1a * z1a;
                const float v1b = prim ? h1b : s1b * z1b;
                *(ull*)&smf[MH2 + lane * 130 + warp * 8 + j] = packf2(v0a, v0b);
                *(ull*)&smf[MH2 + (lane + 32) * 130 + warp * 8 + j] = packf2(v1a, v1b);
            }
        }
        __syncthreads();

        // 5. fwd L3: warps 0..13 -> t-pair
        if (warp < 14) {
            const int t0 = warp * 2;
            ull a4[4] = {0ull, 0ull, 0ull, 0ull};
            const float* x0 = &smf[MH2 + lane * 130];
            const float* x1 = &smf[MH2 + (lane + 32) * 130];
            const float* wb = &smf[W3P + warp * 4];
#pragma unroll 2
            for (int kp = 0; kp < 64; kp++) {
                const ull xa = *(const ull*)(x0 + 2 * kp);
                const ull xb = *(const ull*)(x1 + 2 * kp);
                const double2 wd = *(const double2*)(wb + kp * 56);
                const ull wx = ll(wd.x), wy = ll(wd.y);
                a4[0] = fma2(xa, wx, a4[0]);
                a4[1] = fma2(xa, wy, a4[1]);
                a4[2] = fma2(xb, wx, a4[2]);
                a4[3] = fma2(xb, wy, a4[3]);
            }
            const bool prim = (lane & 1) == 0;
            const float bb0 = prim ? smf[MB3 + t0] : 0.f;
            const float bb1 = prim ? smf[MB3 + t0 + 1] : 0.f;
            smf[MA3 + lane * 30 + t0]            = sum2(a4[0]) + bb0;
            smf[MA3 + lane * 30 + t0 + 1]        = sum2(a4[1]) + bb1;
            smf[MA3 + (lane + 32) * 30 + t0]     = sum2(a4[2]) + bb0;
            smf[MA3 + (lane + 32) * 30 + t0 + 1] = sum2(a4[3]) + bb1;
        }
        __syncthreads();

        // 6. mini-assembly
#pragma unroll 1
        for (int rr = 0; rr < 2; rr++) {
            const int e = rr * 16 + warp;
            if (b0 + e < batch) {
                float dqv = 0.f, ddqv = 0.f;
                if (lane < 7) {
                    dqv = smf[MXIN + e * 24 + 8 + lane];
                    ddqv = smf[MXIN + e * 24 + 16 + lane];
                }
                const float* ap = &smf[MA3 + (2 * e) * 30];
                const float* at = &smf[MA3 + (2 * e + 1) * 30];
                float Lm[28], Db[28], sig[7];
#pragma unroll
                for (int t = 0; t < 28; t++) { Lm[t] = ap[t]; Db[t] = at[t]; }
#pragma unroll
                for (int r = 0; r < 7; r++) {
                    const int td = TRI(r, r);
                    const float p = Lm[td];
                    sig[r] = sigmf(p);
                    Lm[td] = softplusf(p);
                    Db[td] *= sig[r];
                }
                float dqs[7], dds[7];
#pragma unroll
                for (int r = 0; r < 7; r++) {
                    dqs[r] = __shfl_sync(FULL, dqv, r);
                    dds[r] = __shfl_sync(FULL, ddqv, r);
                }
                float u0[7], t2[7], wv[7];
#pragma unroll
                for (int c = 0; c < 7; c++) {
                    float s = 0.f, s2 = 0.f, s3 = 0.f;
#pragma unroll
                    for (int r = 0; r < 7; r++) {
                        if (r >= c) {
                            const int t = TRI(r, c);
                            s = fmaf(Lm[t], dqs[r], s);
                            s2 = fmaf(Lm[t], dds[r], s2);
                            s3 = fmaf(Db[t], dqs[r], s3);
                        }
                    }
                    u0[c] = s; t2[c] = s2; wv[c] = s3;
                }
                float tsel = 0.f;
#pragma unroll
                for (int i = 0; i < 7; i++) {
                    float s = 0.f;
#pragma unroll
                    for (int c = 0; c <= i; c++) {
                        s = fmaf(Lm[TRI(i, c)], t2[c] + wv[c], s);
                        s = fmaf(Db[TRI(i, c)], u0[c], s);
                    }
                    if (lane == i) tsel = s;
                }
                if (lane < 7) smf[MTA + e * 8 + lane] = tsel;
                if (lane < 28) {
                    const int r = TRIR[lane], c = TRIC[lane];
                    float g = dqs[r] * u0[c];
                    if (r == c) g *= sig[r];
                    smf[MGH + e * 29 + lane] = g;
                }
            }
        }
        __syncthreads();

        // 7. bwd L3 (splat, widened): warp -> 4 i-pairs, lane = element
        {
            ull acc[4] = {0ull, 0ull, 0ull, 0ull};
            const float* gh = &smf[MGH + lane * 29];
#pragma unroll
            for (int tp = 0; tp < 14; tp++) {
                const float g0 = gh[2 * tp], g1 = gh[2 * tp + 1];
                const ull s0 = packf2(g0, g0), s1 = packf2(g1, g1);
#pragma unroll
                for (int m = 0; m < 4; m++) {
                    const double2 wd = *(const double2*)&smf[W3P + (warp * 4 + m) * 56 + 4 * tp];
                    acc[m] = fma2(s0, ll(wd.x), acc[m]);
                    acc[m] = fma2(s1, ll(wd.y), acc[m]);
                }
            }
#pragma unroll
            for (int m = 0; m < 4; m++) {
                float ba, bb; unpk2(acc[m], ba, bb);
                const int i0 = warp * 8 + 2 * m;
                float h0, h1;
                unpk2(*(const ull*)&smf[MH2 + (2 * lane) * 130 + i0], h0, h1);
                *(ull*)&smf[BZ2 + lane * 130 + i0] =
                    packf2((1.f - h0 * h0) * ba, (1.f - h1 * h1) * bb);
            }
        }
        __syncthreads();

        // 8. bwd L2 (splat, widened): warp -> 4 k-pairs, lane = element
        {
            ull acc[4] = {0ull, 0ull, 0ull, 0ull};
            const float* bz = &smf[BZ2 + lane * 130];
#pragma unroll 2
            for (int ip = 0; ip < 64; ip++) {
                float b0, b1; unpk2(*(const ull*)(bz + 2 * ip), b0, b1);
                const ull s0 = packf2(b0, b0), s1 = packf2(b1, b1);
#pragma unroll
                for (int m = 0; m < 4; m++) {
                    const double2 wd = *(const double2*)&smf[W2P + (warp * 4 + m) * 256 + 4 * ip];
                    acc[m] = fma2(s0, ll(wd.x), acc[m]);
                    acc[m] = fma2(s1, ll(wd.y), acc[m]);
                }
            }
#pragma unroll
            for (int m = 0; m < 4; m++) {
                float ba, bb; unpk2(acc[m], ba, bb);
                const int k0 = warp * 8 + 2 * m;
                float h0, h1;
                unpk2(*(const ull*)&smf[MH1 + (2 * lane) * 130 + k0], h0, h1);
                *(ull*)&smf[BZ1 + lane * 130 + k0] =
                    packf2((1.f - h0 * h0) * ba, (1.f - h1 * h1) * bb);
            }
        }
        __syncthreads();

        // 9. bwd L1 + gradV + output
#pragma unroll 1
        for (int rr = 0; rr < 2; rr++) {
            const int e = rr * 16 + warp;
            const int b = b0 + e;
            if (b < batch) {
                float qv = 0.f;
                if (lane < 7) qv = smf[MXIN + e * 24 + lane];
                float qs[7];
#pragma unroll
                for (int r = 0; r < 7; r++) qs[r] = __shfl_sync(FULL, qv, r);
                float acc7[7] = {0.f, 0.f, 0.f, 0.f, 0.f, 0.f, 0.f};
#pragma unroll
                for (int m4 = 0; m4 < 4; m4++) {
                    const int k = m4 * 32 + lane;
                    const float bv = smf[BZ1 + e * 130 + k];
#pragma unroll
                    for (int j = 0; j < 7; j++) acc7[j] = fmaf(-smf[MW1 + j * 128 + k], bv, acc7[j]);
                }
#pragma unroll
                for (int hh = 0; hh < 4; hh++) {
                    const int h = hh * 32 + lane;
                    float wvv[7];
                    float z = smf[PB + h];
#pragma unroll
                    for (int d = 0; d < 7; d++) {
                        wvv[d] = smf[PW + d * 128 + h];
                        z = fmaf(qs[d], wvv[d], z);
                    }
                    const float s = sigmf(z) * smf[SP2 + h];
#pragma unroll
                    for (int d = 0; d < 7; d++) acc7[d] = fmaf(wvv[d], s, acc7[d]);
                }
#pragma unroll
                for (int j = 0; j < 7; j++) {
                    acc7[j] += __shfl_xor_sync(FULL, acc7[j], 16);
                    acc7[j] += __shfl_xor_sync(FULL, acc7[j], 8);
                    acc7[j] += __shfl_xor_sync(FULL, acc7[j], 4);
                    acc7[j] += __shfl_xor_sync(FULL, acc7[j], 2);
                    acc7[j] += __shfl_xor_sync(FULL, acc7[j], 1);
                }
                float sel = 0.f;
#pragma unroll
                for (int j = 0; j < 7; j++) if (lane == j) sel = acc7[j];
                if (lane < 7) out[b * 7 + lane] = smf[MTA + e * 8 + lane] + sel;
            }
        }
        __syncthreads();
    }
}

// =====================================================================
// k_damp: R12 two-group version (measured 270us).
// =====================================================================
#define DW1   0
#define DB1   1792
#define DB2   1920
#define DW2P  2048
#define DW3P  18432
#define DB3   22016
#define DGRP  22048
#define DGSZ  16640
#define dH1   0
#define dH2   8320
#define D_TOT (DGRP + 2 * DGSZ)

__global__ __launch_bounds__(512, 1) void k_damp(
    const float* __restrict__ q, const float* __restrict__ dq,
    const float* __restrict__ dW1, const float* __restrict__ db1,
    const float* __restrict__ dW2, const float* __restrict__ db2,
    const float* __restrict__ dW3, const float* __restrict__ db3,
    float* __restrict__ out, int batch)
{
    extern __shared__ float smf[];
    const int tid = threadIdx.x;
    const int lane = tid & 31;
    const int warp = tid >> 5;
    const int grp = warp >> 3;
    const int wg = warp & 7;

    for (int i = tid; i < 1792; i += 512) smf[DW1 + i] = dW1[i];
    for (int i = tid; i < 128; i += 512) { smf[DB1 + i] = db1[i]; smf[DB2 + i] = db2[i]; }
    for (int idx = tid; idx < 16384; idx += 512) {
        const int kp = idx >> 8, r = idx & 255;
        smf[DW2P + idx] = dW2[(2 * kp + (r & 1)) * 128 + (r >> 1)];
    }
    for (int idx = tid; idx < 3584; idx += 512) {
        const int kp = idx / 56, r = idx % 56;
        smf[DW3P + idx] = dW3[(2 * kp + (r & 1)) * 28 + (r >> 1)];
    }
    for (int i = tid; i < 32; i += 512) smf[DB3 + i] = (i < 28) ? db3[i] : 0.f;
    __syncthreads();

    float* g = smf + DGRP + grp * DGSZ;
    const int gt = tid & 255;
    const int i1 = tid & 127;
    const int eh = (tid >> 7) & 1;
    float w1r[14];
#pragma unroll
    for (int d = 0; d < 14; d++) w1r[d] = smf[DW1 + d * 128 + i1];
    const float b1r = smf[DB1 + i1];

    const int ntiles = (batch + 63) >> 6;
    for (int tile = blockIdx.x * 2 + grp; tile < ntiles; tile += gridDim.x * 2) {
        const int b0 = tile << 6;

        for (int idx = gt; idx < 896; idx += 256) {
            const int e = idx / 14, d = idx % 14;
            const int b = b0 + e;
            float v = 0.f;
            if (b < batch) v = (d < 7) ? q[b * 7 + d] : dq[b * 7 + d - 7];
            g[dH2 + idx] = v;
        }
        GBAR();

#pragma unroll 2
        for (int it = 0; it < 32; it++) {
            const int e = eh * 32 + it;
            const float* xe = g + dH2 + e * 14;
            float z = b1r;
#pragma unroll
            for (int d = 0; d < 14; d++) z = fmaf(xe[d], w1r[d], z);
            g[dH1 + e * 130 + i1] = tanh_fast(z);
        }
        GBAR();

        {
            ull acc0[16], acc1[16];
#pragma unroll
            for (int ii = 0; ii < 16; ii++) { acc0[ii] = 0ull; acc1[ii] = 0ull; }
            const float* x0 = g + dH1 + lane * 130;
            const float* x1 = g + dH1 + (lane + 32) * 130;
            const float* wb = smf + DW2P + wg * 32;
#pragma unroll 1
            for (int kp = 0; kp < 64; kp++) {
                const ull xa = *(const ull*)(x0 + 2 * kp);
                const ull xb = *(const ull*)(x1 + 2 * kp);
                const float* wr = wb + kp * 256;
#pragma unroll
                for (int m = 0; m < 8; m++) {
                    const double2 wd = *(const double2*)(wr + 4 * m);
                    const ull wx = ll(wd.x), wy = ll(wd.y);
                    acc0[2 * m]     = fma2(xa, wx, acc0[2 * m]);
                    acc1[2 * m]     = fma2(xb, wx, acc1[2 * m]);
                    acc0[2 * m + 1] = fma2(xa, wy, acc0[2 * m + 1]);
                    acc1[2 * m + 1] = fma2(xb, wy, acc1[2 * m + 1]);
                }
            }
            float* y0 = g + dH2 + lane * 130 + wg * 16;
            float* y1 = g + dH2 + (lane + 32) * 130 + wg * 16;
#pragma unroll
            for (int m = 0; m < 8; m++) {
                const float ba = smf[DB2 + wg * 16 + 2 * m];
                const float bb = smf[DB2 + wg * 16 + 2 * m + 1];
                const float v0a = tanh_fast(sum2(acc0[2 * m]) + ba);
                const float v0b = tanh_fast(sum2(acc0[2 * m + 1]) + bb);
                const float v1a = tanh_fast(sum2(acc1[2 * m]) + ba);
                const float v1b = tanh_fast(sum2(acc1[2 * m + 1]) + bb);
                *(ull*)(y0 + 2 * m) = packf2(v0a, v0b);
                *(ull*)(y1 + 2 * m) = packf2(v1a, v1b);
            }
        }
        GBAR();

        if (wg < 7) {
            ull a0[4] = {0,0,0,0}, a1[4] = {0,0,0,0};
            const float* x0 = g + dH2 + lane * 130;
            const float* x1 = g + dH2 + (lane + 32) * 130;
            const float* wb = smf + DW3P + wg * 8;
#pragma unroll 1
            for (int kp = 0; kp < 64; kp++) {
                const ull xa = *(const ull*)(x0 + 2 * kp);
                const ull xb = *(const ull*)(x1 + 2 * kp);
                const double2 w0 = *(const double2*)(wb + kp * 56);
                const double2 w1 = *(const double2*)(wb + kp * 56 + 4);
                const ull wA = ll(w0.x), wB = ll(w0.y);
                const ull wC = ll(w1.x), wD = ll(w1.y);
                a0[0] = fma2(xa, wA, a0[0]); a1[0] = fma2(xb, wA, a1[0]);
                a0[1] = fma2(xa, wB, a0[1]); a1[1] = fma2(xb, wB, a1[1]);
                a0[2] = fma2(xa, wC, a0[2]); a1[2] = fma2(xb, wC, a1[2]);
                a0[3] = fma2(xa, wD, a0[3]); a1[3] = fma2(xb, wD, a1[3]);
            }
#pragma unroll
            for (int j = 0; j < 4; j++) {
                const int i = wg * 4 + j;
                const float bb = smf[DB3 + i];
                g[dH1 + lane * 33 + i] = sum2(a0[j]) + bb;
                g[dH1 + (lane + 32) * 33 + i] = sum2(a1[j]) + bb;
            }
        }
        GBAR();

#pragma unroll 1
        for (int rr = 0; rr < 8; rr++) {
            const int e = rr * 8 + wg;
            const int b = b0 + e;
            if (b < batch) {
                float dqv = 0.f;
                if (lane < 7) dqv = dq[b * 7 + lane];
                float dqs[7];
#pragma unroll
                for (int r = 0; r < 7; r++) dqs[r] = __shfl_sync(FULL, dqv, r);
                const float* scr = g + dH1 + e * 33;
                float Lm[28];
#pragma unroll
                for (int t = 0; t < 28; t++) Lm[t] = scr[t];
#pragma unroll
                for (int r = 0; r < 7; r++) Lm[TRI(r, r)] = softplusf(Lm[TRI(r, r)]);
                float u[7];
#pragma unroll
                for (int c = 0; c < 7; c++) {
                    float s = 0.f;
#pragma unroll
                    for (int r = 0; r < 7; r++)
                        if (r >= c) s = fmaf(Lm[TRI(r, c)], dqs[r], s);
                    u[c] = s;
                }
                float outsel = 0.f;
#pragma unroll
                for (int i = 0; i < 7; i++) {
                    float s = 0.f;
#pragma unroll
                    for (int c = 0; c <= i; c++) s = fmaf(Lm[TRI(i, c)], u[c], s);
                    if (lane == i) outsel = s;
                }
                if (lane < 7) out[b * 7 + lane] += outsel;
            }
        }
        GBAR();
    }
}

// =====================================================================
extern "C" void kernel_launch(void* const* d_in, const int* in_sizes, int n_in,
                              void* d_out, int out_size)
{
    const float* q   = (const float*)d_in[0];
    const float* dq  = (const float*)d_in[1];
    const float* ddq = (const float*)d_in[2];
    const float* mW1 = (const float*)d_in[3];
    const float* mb1 = (const float*)d_in[4];
    const float* mW2 = (const float*)d_in[5];
    const float* mb2 = (const float*)d_in[6];
    const float* mW3 = (const float*)d_in[7];
    const float* mb3 = (const float*)d_in[8];
    const float* dW1 = (const float*)d_in[9];
    const float* db1 = (const float*)d_in[10];
    const float* dW2 = (const float*)d_in[11];
    const float* db2 = (const float*)d_in[12];
    const float* dW3 = (const float*)d_in[13];
    const float* db3 = (const float*)d_in[14];
    const float* pW1 = (const float*)d_in[15];
    const float* pb1 = (const float*)d_in[16];
    const float* pw2 = (const float*)d_in[17];
    float* out = (float*)d_out;

    const int batch = in_sizes[0] / 7;

    const size_t sm1 = (size_t)M_TOT * sizeof(float);
    const size_t sm2 = (size_t)D_TOT * sizeof(float);

    cudaFuncSetAttribute(k_mass, cudaFuncAttributeMaxDynamicSharedMemorySize, (int)sm1);
    cudaFuncSetAttribute(k_damp, cudaFuncAttributeMaxDynamicSharedMemorySize, (int)sm2);

    k_mass<<<148, 512, sm1>>>(q, dq, ddq, mW1, mb1, mW2, mb2, mW3, mb3,
                              pW1, pb1, pw2, out, batch);
    k_damp<<<148, 512, sm2>>>(q, dq, dW1, db1, dW2, db2, dW3, db3, out, batch);
}

// round 14
// speedup vs baseline: 1.2327x; 1.1712x over previous
#include <cuda_runtime.h>
#include <math.h>

#define FULL 0xffffffffu
typedef unsigned long long ull;
typedef unsigned int u32;

static __device__ __forceinline__ float softplusf(float x) {
    return fmaxf(x, 0.f) + log1pf(expf(-fabsf(x)));
}
static __device__ __forceinline__ float sigmf(float x) {
    return __fdividef(1.f, 1.f + __expf(-x));
}
static __device__ __forceinline__ float tanh_fast(float x) {
    const float e = __expf(2.f * x);
    return 1.f - __fdividef(2.f, e + 1.f);
}
__host__ __device__ constexpr int TRI(int r, int c) { return r * (r + 1) / 2 + c; }

static __device__ __forceinline__ ull fma2(ull a, ull b, ull c) {
    ull d;
    asm("fma.rn.f32x2 %0, %1, %2, %3;" : "=l"(d) : "l"(a), "l"(b), "l"(c));
    return d;
}
static __device__ __forceinline__ float sum2(ull v) {
    u32 l, h;
    asm("mov.b64 {%0, %1}, %2;" : "=r"(l), "=r"(h) : "l"(v));
    return __uint_as_float(l) + __uint_as_float(h);
}
static __device__ __forceinline__ void unpk2(ull v, float& a, float& b) {
    u32 l, h;
    asm("mov.b64 {%0, %1}, %2;" : "=r"(l), "=r"(h) : "l"(v));
    a = __uint_as_float(l); b = __uint_as_float(h);
}
static __device__ __forceinline__ ull packf2(float lo, float hi) {
    ull d;
    asm("mov.b64 %0, {%1, %2};" : "=l"(d) : "r"(__float_as_uint(lo)), "r"(__float_as_uint(hi)));
    return d;
}
static __device__ __forceinline__ ull ll(double d) { return __double_as_longlong(d); }
#define GBAR() asm volatile("bar.sync %0, 256;" :: "r"(grp + 1) : "memory")

__device__ __constant__ int TRIR[28] = {0,1,1,2,2,2,3,3,3,3,4,4,4,4,4,5,5,5,5,5,5,6,6,6,6,6,6,6};
__device__ __constant__ int TRIC[28] = {0,0,1,0,1,2,0,1,2,3,0,1,2,3,4,0,1,2,3,4,5,0,1,2,3,4,5,6};

// =====================================================================
// k_mass: JVP+VJP+gradV. Tile = 32 elements, 64 fwd rows. 512 thr.
// Phase 6 is element-per-lane scalar (no duplication, no shuffles).
// =====================================================================
#define MW1   0
#define MB1   896
#define MB2   1024
#define MB3   1152
#define PW    1184
#define PB    2080
#define SP2   2208
#define W2P   2336
#define W3P   18720
#define MXIN  22304
#define MH1   23072
#define MH2   31392
#define MA3   39712
#define MGH   41632
#define MTA   42560
#define BZ2   42816
#define BZ1   46976
#define M_TOT 51136

__global__ __launch_bounds__(512, 1) void k_mass(
    const float* __restrict__ q, const float* __restrict__ dq, const float* __restrict__ ddq,
    const float* __restrict__ mW1, const float* __restrict__ mb1,
    const float* __restrict__ mW2, const float* __restrict__ mb2,
    const float* __restrict__ mW3, const float* __restrict__ mb3,
    const float* __restrict__ pW1, const float* __restrict__ pb1,
    const float* __restrict__ pw2,
    float* __restrict__ out, int batch)
{
    extern __shared__ float smf[];
    const int tid = threadIdx.x;
    const int lane = tid & 31;
    const int warp = tid >> 5;

    for (int i = tid; i < 896; i += 512) { smf[MW1 + i] = mW1[i]; smf[PW + i] = pW1[i]; }
    for (int i = tid; i < 128; i += 512) {
        smf[MB1 + i] = mb1[i]; smf[MB2 + i] = mb2[i];
        smf[PB + i] = pb1[i]; smf[SP2 + i] = softplusf(pw2[i]);
    }
    for (int i = tid; i < 32; i += 512) smf[MB3 + i] = (i < 28) ? mb3[i] : 0.f;
    for (int idx = tid; idx < 16384; idx += 512) {
        const int kp = idx >> 8, r = idx & 255;
        smf[W2P + idx] = mW2[(2 * kp + (r & 1)) * 128 + (r >> 1)];
    }
    for (int idx = tid; idx < 3584; idx += 512) {
        const int kp = idx / 56, r = idx % 56;
        smf[W3P + idx] = mW3[(2 * kp + (r & 1)) * 28 + (r >> 1)];
    }
    __syncthreads();

    const int i1 = tid & 127;
    const int eg = tid >> 7;
    float w1r[7];
#pragma unroll
    for (int d = 0; d < 7; d++) w1r[d] = smf[MW1 + d * 128 + i1];
    const float b1r = smf[MB1 + i1];

    const int ntiles = (batch + 31) >> 5;
    for (int tile = blockIdx.x; tile < ntiles; tile += gridDim.x) {
        const int b0 = tile << 5;

        // 1. stage XIN
        for (int idx = tid; idx < 768; idx += 512) {
            const int e = idx / 24, s = idx % 24;
            const int b = b0 + e;
            float v = 0.f;
            if (b < batch) {
                if (s < 7) v = q[b * 7 + s];
                else if (s >= 8 && s < 15) v = dq[b * 7 + s - 8];
                else if (s >= 16 && s < 23) v = ddq[b * 7 + s - 16];
            }
            smf[MXIN + idx] = v;
        }
        __syncthreads();

        // 2. layer1 primal + tangent (vectorized input reads)
#pragma unroll
        for (int it = 0; it < 8; it++) {
            const int e = eg * 8 + it;
            const float* xe = &smf[MXIN + e * 24];
            const float4 x0v = *(const float4*)(xe);
            const float4 x1v = *(const float4*)(xe + 4);
            const float4 x2v = *(const float4*)(xe + 8);
            const float4 x3v = *(const float4*)(xe + 12);
            float z = b1r, dz = 0.f;
            z = fmaf(x0v.x, w1r[0], z); z = fmaf(x0v.y, w1r[1], z);
            z = fmaf(x0v.z, w1r[2], z); z = fmaf(x0v.w, w1r[3], z);
            z = fmaf(x1v.x, w1r[4], z); z = fmaf(x1v.y, w1r[5], z);
            z = fmaf(x1v.z, w1r[6], z);
            dz = fmaf(x2v.x, w1r[0], dz); dz = fmaf(x2v.y, w1r[1], dz);
            dz = fmaf(x2v.z, w1r[2], dz); dz = fmaf(x2v.w, w1r[3], dz);
            dz = fmaf(x3v.x, w1r[4], dz); dz = fmaf(x3v.y, w1r[5], dz);
            dz = fmaf(x3v.z, w1r[6], dz);
            const float h = tanh_fast(z);
            smf[MH1 + (2 * e) * 130 + i1] = h;
            smf[MH1 + (2 * e + 1) * 130 + i1] = (1.f - h * h) * dz;
        }
        __syncthreads();

        // 3. fwd L2: warp -> 8 outs, lane rows (lane, lane+32)
        {
            ull acc[16];
#pragma unroll
            for (int m = 0; m < 16; m++) acc[m] = 0ull;
            const float* x0 = &smf[MH1 + lane * 130];
            const float* x1 = &smf[MH1 + (lane + 32) * 130];
            const float* wb = &smf[W2P + warp * 16];
#pragma unroll 2
            for (int kp = 0; kp < 64; kp++) {
                const ull xa = *(const ull*)(x0 + 2 * kp);
                const ull xb = *(const ull*)(x1 + 2 * kp);
                const float* wr = wb + kp * 256;
#pragma unroll
                for (int m = 0; m < 4; m++) {
                    const double2 wd = *(const double2*)(wr + 4 * m);
                    const ull wx = ll(wd.x), wy = ll(wd.y);
                    acc[2 * m]         = fma2(xa, wx, acc[2 * m]);
                    acc[2 * m + 1]     = fma2(xa, wy, acc[2 * m + 1]);
                    acc[8 + 2 * m]     = fma2(xb, wx, acc[8 + 2 * m]);
                    acc[8 + 2 * m + 1] = fma2(xb, wy, acc[8 + 2 * m + 1]);
                }
            }
            // 4. epilogue
            const int psrc = lane & ~1;
            const bool prim = (lane & 1) == 0;
#pragma unroll
            for (int j = 0; j < 8; j += 2) {
                const float z0a = sum2(acc[j]),     z0b = sum2(acc[j + 1]);
                const float z1a = sum2(acc[8 + j]), z1b = sum2(acc[8 + j + 1]);
                float h0a = 0.f, h0b = 0.f, h1a = 0.f, h1b = 0.f;
                float g0a = 0.f, g0b = 0.f, g1a = 0.f, g1b = 0.f;
                if (prim) {
                    const float ba = smf[MB2 + warp * 8 + j];
                    const float bb = smf[MB2 + warp * 8 + j + 1];
                    h0a = tanh_fast(z0a + ba); g0a = 1.f - h0a * h0a;
                    h0b = tanh_fast(z0b + bb); g0b = 1.f - h0b * h0b;
                    h1a = tanh_fast(z1a + ba); g1a = 1.f - h1a * h1a;
                    h1b = tanh_fast(z1b + bb); g1b = 1.f - h1b * h1b;
                }
                const float s0a = __shfl_sync(FULL, g0a, psrc);
                const float s0b = __shfl_sync(FULL, g0b, psrc);
                const float s1a = __shfl_sync(FULL, g1a, psrc);
                const float s1b = __shfl_sync(FULL, g1b, psrc);
                const float v0a = prim ? h0a : s0a * z0a;
                const float v0b = prim ? h0b : s0b * z0b;
                const float v1a = prim ? h1a : s1a * z1a;
                const float v1b = prim ? h1b : s1b * z1b;
                *(ull*)&smf[MH2 + lane * 130 + warp * 8 + j] = packf2(v0a, v0b);
                *(ull*)&smf[MH2 + (lane + 32) * 130 + warp * 8 + j] = packf2(v1a, v1b);
            }
        }
        __syncthreads();

        // 5. fwd L3: warps 0..13 -> t-pair
        if (warp < 14) {
            const int t0 = warp * 2;
            ull a4[4] = {0ull, 0ull, 0ull, 0ull};
            const float* x0 = &smf[MH2 + lane * 130];
            const float* x1 = &smf[MH2 + (lane + 32) * 130];
            const float* wb = &smf[W3P + warp * 4];
#pragma unroll 2
            for (int kp = 0; kp < 64; kp++) {
                const ull xa = *(const ull*)(x0 + 2 * kp);
                const ull xb = *(const ull*)(x1 + 2 * kp);
                const double2 wd = *(const double2*)(wb + kp * 56);
                const ull wx = ll(wd.x), wy = ll(wd.y);
                a4[0] = fma2(xa, wx, a4[0]);
                a4[1] = fma2(xa, wy, a4[1]);
                a4[2] = fma2(xb, wx, a4[2]);
                a4[3] = fma2(xb, wy, a4[3]);
            }
            const bool prim = (lane & 1) == 0;
            const float bb0 = prim ? smf[MB3 + t0] : 0.f;
            const float bb1 = prim ? smf[MB3 + t0 + 1] : 0.f;
            smf[MA3 + lane * 30 + t0]            = sum2(a4[0]) + bb0;
            smf[MA3 + lane * 30 + t0 + 1]        = sum2(a4[1]) + bb1;
            smf[MA3 + (lane + 32) * 30 + t0]     = sum2(a4[2]) + bb0;
            smf[MA3 + (lane + 32) * 30 + t0 + 1] = sum2(a4[3]) + bb1;
        }
        __syncthreads();

        // 6. mini-assembly: ELEMENT-PER-LANE (warps 0-3, lanes 0-7)
        if (warp < 4 && lane < 8) {
            const int e = warp * 8 + lane;
            if (b0 + e < batch) {
                const float* xe = &smf[MXIN + e * 24];
                float dqs[7], dds[7];
#pragma unroll
                for (int r = 0; r < 7; r++) { dqs[r] = xe[8 + r]; dds[r] = xe[16 + r]; }
                const float* ap = &smf[MA3 + (2 * e) * 30];
                const float* at = ap + 30;
                float Lm[28], Db[28], sig[7];
#pragma unroll
                for (int t = 0; t < 28; t++) { Lm[t] = ap[t]; Db[t] = at[t]; }
#pragma unroll
                for (int r = 0; r < 7; r++) {
                    const int td = TRI(r, r);
                    const float p = Lm[td];
                    sig[r] = sigmf(p);
                    Lm[td] = softplusf(p);
                    Db[td] *= sig[r];
                }
                float u0[7], t2[7], wv[7];
#pragma unroll
                for (int c = 0; c < 7; c++) {
                    float s = 0.f, s2 = 0.f, s3 = 0.f;
#pragma unroll
                    for (int r = 0; r < 7; r++) {
                        if (r >= c) {
                            const int t = TRI(r, c);
                            s = fmaf(Lm[t], dqs[r], s);
                            s2 = fmaf(Lm[t], dds[r], s2);
                            s3 = fmaf(Db[t], dqs[r], s3);
                        }
                    }
                    u0[c] = s; t2[c] = s2; wv[c] = s3;
                }
#pragma unroll
                for (int i = 0; i < 7; i++) {
                    float s = 0.f;
#pragma unroll
                    for (int c = 0; c <= i; c++) {
                        s = fmaf(Lm[TRI(i, c)], t2[c] + wv[c], s);
                        s = fmaf(Db[TRI(i, c)], u0[c], s);
                    }
                    smf[MTA + e * 8 + i] = s;
                }
#pragma unroll
                for (int t = 0; t < 28; t++) {
                    const int r = TRIR[t], c = TRIC[t];
                    float g = dqs[r] * u0[c];
                    if (r == c) g *= sig[r];
                    smf[MGH + e * 29 + t] = g;
                }
            }
        }
        __syncthreads();

        // 7. bwd L3 (splat, widened): warp -> 4 i-pairs, lane = element
        {
            ull acc[4] = {0ull, 0ull, 0ull, 0ull};
            const float* gh = &smf[MGH + lane * 29];
#pragma unroll
            for (int tp = 0; tp < 14; tp++) {
                const float g0 = gh[2 * tp], g1 = gh[2 * tp + 1];
                const ull s0 = packf2(g0, g0), s1 = packf2(g1, g1);
#pragma unroll
                for (int m = 0; m < 4; m++) {
                    const double2 wd = *(const double2*)&smf[W3P + (warp * 4 + m) * 56 + 4 * tp];
                    acc[m] = fma2(s0, ll(wd.x), acc[m]);
                    acc[m] = fma2(s1, ll(wd.y), acc[m]);
                }
            }
#pragma unroll
            for (int m = 0; m < 4; m++) {
                float ba, bb; unpk2(acc[m], ba, bb);
                const int i0 = warp * 8 + 2 * m;
                float h0, h1;
                unpk2(*(const ull*)&smf[MH2 + (2 * lane) * 130 + i0], h0, h1);
                *(ull*)&smf[BZ2 + lane * 130 + i0] =
                    packf2((1.f - h0 * h0) * ba, (1.f - h1 * h1) * bb);
            }
        }
        __syncthreads();

        // 8. bwd L2 (splat, widened): warp -> 4 k-pairs, lane = element
        {
            ull acc[4] = {0ull, 0ull, 0ull, 0ull};
            const float* bz = &smf[BZ2 + lane * 130];
#pragma unroll 2
            for (int ip = 0; ip < 64; ip++) {
                float b0v, b1v; unpk2(*(const ull*)(bz + 2 * ip), b0v, b1v);
                const ull s0 = packf2(b0v, b0v), s1 = packf2(b1v, b1v);
#pragma unroll
                for (int m = 0; m < 4; m++) {
                    const double2 wd = *(const double2*)&smf[W2P + (warp * 4 + m) * 256 + 4 * ip];
                    acc[m] = fma2(s0, ll(wd.x), acc[m]);
                    acc[m] = fma2(s1, ll(wd.y), acc[m]);
                }
            }
#pragma unroll
            for (int m = 0; m < 4; m++) {
                float ba, bb; unpk2(acc[m], ba, bb);
                const int k0 = warp * 8 + 2 * m;
                float h0, h1;
                unpk2(*(const ull*)&smf[MH1 + (2 * lane) * 130 + k0], h0, h1);
                *(ull*)&smf[BZ1 + lane * 130 + k0] =
                    packf2((1.f - h0 * h0) * ba, (1.f - h1 * h1) * bb);
            }
        }
        __syncthreads();

        // 9. bwd L1 + gradV + output
#pragma unroll 1
        for (int rr = 0; rr < 2; rr++) {
            const int e = rr * 16 + warp;
            const int b = b0 + e;
            if (b < batch) {
                float qv = 0.f;
                if (lane < 7) qv = smf[MXIN + e * 24 + lane];
                float qs[7];
#pragma unroll
                for (int r = 0; r < 7; r++) qs[r] = __shfl_sync(FULL, qv, r);
                float acc7[7] = {0.f, 0.f, 0.f, 0.f, 0.f, 0.f, 0.f};
#pragma unroll
                for (int m4 = 0; m4 < 4; m4++) {
                    const int k = m4 * 32 + lane;
                    const float bv = smf[BZ1 + e * 130 + k];
#pragma unroll
                    for (int j = 0; j < 7; j++) acc7[j] = fmaf(-smf[MW1 + j * 128 + k], bv, acc7[j]);
                }
#pragma unroll
                for (int hh = 0; hh < 4; hh++) {
                    const int h = hh * 32 + lane;
                    float wvv[7];
                    float z = smf[PB + h];
#pragma unroll
                    for (int d = 0; d < 7; d++) {
                        wvv[d] = smf[PW + d * 128 + h];
                        z = fmaf(qs[d], wvv[d], z);
                    }
                    const float s = sigmf(z) * smf[SP2 + h];
#pragma unroll
                    for (int d = 0; d < 7; d++) acc7[d] = fmaf(wvv[d], s, acc7[d]);
                }
#pragma unroll
                for (int j = 0; j < 7; j++) {
                    acc7[j] += __shfl_xor_sync(FULL, acc7[j], 16);
                    acc7[j] += __shfl_xor_sync(FULL, acc7[j], 8);
                    acc7[j] += __shfl_xor_sync(FULL, acc7[j], 4);
                    acc7[j] += __shfl_xor_sync(FULL, acc7[j], 2);
                    acc7[j] += __shfl_xor_sync(FULL, acc7[j], 1);
                }
                float sel = 0.f;
#pragma unroll
                for (int j = 0; j < 7; j++) if (lane == j) sel = acc7[j];
                if (lane < 7) out[b * 7 + lane] = smf[MTA + e * 8 + lane] + sel;
            }
        }
        __syncthreads();
    }
}

// =====================================================================
// k_damp: two groups of 8 warps; assembly is element-per-lane.
// =====================================================================
#define DW1   0
#define DB1   1792
#define DB2   1920
#define DW2P  2048
#define DW3P  18432
#define DB3   22016
#define DGRP  22048
#define DGSZ  16640
#define dH1   0
#define dH2   8320
#define D_TOT (DGRP + 2 * DGSZ)

__global__ __launch_bounds__(512, 1) void k_damp(
    const float* __restrict__ q, const float* __restrict__ dq,
    const float* __restrict__ dW1, const float* __restrict__ db1,
    const float* __restrict__ dW2, const float* __restrict__ db2,
    const float* __restrict__ dW3, const float* __restrict__ db3,
    float* __restrict__ out, int batch)
{
    extern __shared__ float smf[];
    const int tid = threadIdx.x;
    const int lane = tid & 31;
    const int warp = tid >> 5;
    const int grp = warp >> 3;
    const int wg = warp & 7;

    for (int i = tid; i < 1792; i += 512) smf[DW1 + i] = dW1[i];
    for (int i = tid; i < 128; i += 512) { smf[DB1 + i] = db1[i]; smf[DB2 + i] = db2[i]; }
    for (int idx = tid; idx < 16384; idx += 512) {
        const int kp = idx >> 8, r = idx & 255;
        smf[DW2P + idx] = dW2[(2 * kp + (r & 1)) * 128 + (r >> 1)];
    }
    for (int idx = tid; idx < 3584; idx += 512) {
        const int kp = idx / 56, r = idx % 56;
        smf[DW3P + idx] = dW3[(2 * kp + (r & 1)) * 28 + (r >> 1)];
    }
    for (int i = tid; i < 32; i += 512) smf[DB3 + i] = (i < 28) ? db3[i] : 0.f;
    __syncthreads();

    float* g = smf + DGRP + grp * DGSZ;
    const int gt = tid & 255;
    const int i1 = tid & 127;
    const int eh = (tid >> 7) & 1;
    float w1r[14];
#pragma unroll
    for (int d = 0; d < 14; d++) w1r[d] = smf[DW1 + d * 128 + i1];
    const float b1r = smf[DB1 + i1];

    const int ntiles = (batch + 63) >> 6;
    for (int tile = blockIdx.x * 2 + grp; tile < ntiles; tile += gridDim.x * 2) {
        const int b0 = tile << 6;

        for (int idx = gt; idx < 896; idx += 256) {
            const int e = idx / 14, d = idx % 14;
            const int b = b0 + e;
            float v = 0.f;
            if (b < batch) v = (d < 7) ? q[b * 7 + d] : dq[b * 7 + d - 7];
            g[dH2 + idx] = v;
        }
        GBAR();

#pragma unroll 2
        for (int it = 0; it < 32; it++) {
            const int e = eh * 32 + it;
            const float2* xv = (const float2*)(g + dH2 + e * 14);
            float z = b1r;
#pragma unroll
            for (int p = 0; p < 7; p++) {
                const float2 v = xv[p];
                z = fmaf(v.x, w1r[2 * p], z);
                z = fmaf(v.y, w1r[2 * p + 1], z);
            }
            g[dH1 + e * 130 + i1] = tanh_fast(z);
        }
        GBAR();

        {
            ull acc0[16], acc1[16];
#pragma unroll
            for (int ii = 0; ii < 16; ii++) { acc0[ii] = 0ull; acc1[ii] = 0ull; }
            const float* x0 = g + dH1 + lane * 130;
            const float* x1 = g + dH1 + (lane + 32) * 130;
            const float* wb = smf + DW2P + wg * 32;
#pragma unroll 1
            for (int kp = 0; kp < 64; kp++) {
                const ull xa = *(const ull*)(x0 + 2 * kp);
                const ull xb = *(const ull*)(x1 + 2 * kp);
                const float* wr = wb + kp * 256;
#pragma unroll
                for (int m = 0; m < 8; m++) {
                    const double2 wd = *(const double2*)(wr + 4 * m);
                    const ull wx = ll(wd.x), wy = ll(wd.y);
                    acc0[2 * m]     = fma2(xa, wx, acc0[2 * m]);
                    acc1[2 * m]     = fma2(xb, wx, acc1[2 * m]);
                    acc0[2 * m + 1] = fma2(xa, wy, acc0[2 * m + 1]);
                    acc1[2 * m + 1] = fma2(xb, wy, acc1[2 * m + 1]);
                }
            }
            float* y0 = g + dH2 + lane * 130 + wg * 16;
            float* y1 = g + dH2 + (lane + 32) * 130 + wg * 16;
#pragma unroll
            for (int m = 0; m < 8; m++) {
                const float ba = smf[DB2 + wg * 16 + 2 * m];
                const float bb = smf[DB2 + wg * 16 + 2 * m + 1];
                const float v0a = tanh_fast(sum2(acc0[2 * m]) + ba);
                const float v0b = tanh_fast(sum2(acc0[2 * m + 1]) + bb);
                const float v1a = tanh_fast(sum2(acc1[2 * m]) + ba);
                const float v1b = tanh_fast(sum2(acc1[2 * m + 1]) + bb);
                *(ull*)(y0 + 2 * m) = packf2(v0a, v0b);
                *(ull*)(y1 + 2 * m) = packf2(v1a, v1b);
            }
        }
        GBAR();

        if (wg < 7) {
            ull a0[4] = {0,0,0,0}, a1[4] = {0,0,0,0};
            const float* x0 = g + dH2 + lane * 130;
            const float* x1 = g + dH2 + (lane + 32) * 130;
            const float* wb = smf + DW3P + wg * 8;
#pragma unroll 1
            for (int kp = 0; kp < 64; kp++) {
                const ull xa = *(const ull*)(x0 + 2 * kp);
                const ull xb = *(const ull*)(x1 + 2 * kp);
                const double2 w0 = *(const double2*)(wb + kp * 56);
                const double2 w1 = *(const double2*)(wb + kp * 56 + 4);
                const ull wA = ll(w0.x), wB = ll(w0.y);
                const ull wC = ll(w1.x), wD = ll(w1.y);
                a0[0] = fma2(xa, wA, a0[0]); a1[0] = fma2(xb, wA, a1[0]);
                a0[1] = fma2(xa, wB, a0[1]); a1[1] = fma2(xb, wB, a1[1]);
                a0[2] = fma2(xa, wC, a0[2]); a1[2] = fma2(xb, wC, a1[2]);
                a0[3] = fma2(xa, wD, a0[3]); a1[3] = fma2(xb, wD, a1[3]);
            }
#pragma unroll
            for (int j = 0; j < 4; j++) {
                const int i = wg * 4 + j;
                const float bb = smf[DB3 + i];
                g[dH1 + lane * 33 + i] = sum2(a0[j]) + bb;
                g[dH1 + (lane + 32) * 33 + i] = sum2(a1[j]) + bb;
            }
        }
        GBAR();

        // assembly: ELEMENT-PER-LANE (warps wg<2; e = wg*32+lane)
        if (wg < 2) {
            const int e = wg * 32 + lane;
            const int b = b0 + e;
            if (b < batch) {
                float dqs[7];
#pragma unroll
                for (int r = 0; r < 7; r++) dqs[r] = dq[b * 7 + r];
                const float* scr = g + dH1 + e * 33;
                float Lm[28];
#pragma unroll
                for (int t = 0; t < 28; t++) Lm[t] = scr[t];
#pragma unroll
                for (int r = 0; r < 7; r++) Lm[TRI(r, r)] = softplusf(Lm[TRI(r, r)]);
                float u[7];
#pragma unroll
                for (int c = 0; c < 7; c++) {
                    float s = 0.f;
#pragma unroll
                    for (int r = 0; r < 7; r++)
                        if (r >= c) s = fmaf(Lm[TRI(r, c)], dqs[r], s);
                    u[c] = s;
                }
#pragma unroll
                for (int i = 0; i < 7; i++) {
                    float s = 0.f;
#pragma unroll
                    for (int c = 0; c <= i; c++) s = fmaf(Lm[TRI(i, c)], u[c], s);
                    out[b * 7 + i] += s;
                }
            }
        }
        GBAR();
    }
}

// =====================================================================
extern "C" void kernel_launch(void* const* d_in, const int* in_sizes, int n_in,
                              void* d_out, int out_size)
{
    const float* q   = (const float*)d_in[0];
    const float* dq  = (const float*)d_in[1];
    const float* ddq = (const float*)d_in[2];
    const float* mW1 = (const float*)d_in[3];
    const float* mb1 = (const float*)d_in[4];
    const float* mW2 = (const float*)d_in[5];
    const float* mb2 = (const float*)d_in[6];
    const float* mW3 = (const float*)d_in[7];
    const float* mb3 = (const float*)d_in[8];
    const float* dW1 = (const float*)d_in[9];
    const float* db1 = (const float*)d_in[10];
    const float* dW2 = (const float*)d_in[11];
    const float* db2 = (const float*)d_in[12];
    const float* dW3 = (const float*)d_in[13];
    const float* db3 = (const float*)d_in[14];
    const float* pW1 = (const float*)d_in[15];
    const float* pb1 = (const float*)d_in[16];
    const float* pw2 = (const float*)d_in[17];
    float* out = (float*)d_out;

    const int batch = in_sizes[0] / 7;

    const size_t sm1 = (size_t)M_TOT * sizeof(float);
    const size_t sm2 = (size_t)D_TOT * sizeof(float);

    cudaFuncSetAttribute(k_mass, cudaFuncAttributeMaxDynamicSharedMemorySize, (int)sm1);
    cudaFuncSetAttribute(k_damp, cudaFuncAttributeMaxDynamicSharedMemorySize, (int)sm2);

    k_mass<<<148, 512, sm1>>>(q, dq, ddq, mW1, mb1, mW2, mb2, mW3, mb3,
                              pW1, pb1, pw2, out, batch);
    k_damp<<<148, 512, sm2>>>(q, dq, dW1, db1, dW2, db2, dW3, db3, out, batch);
}